// round 12
// baseline (speedup 1.0000x reference)
#include <cuda_runtime.h>
#include <math.h>

#define Bn    256
#define Cn    112
#define C2    224
#define Pn    200
#define Dn    10
#define NCLSn 200
#define NPAIR 112
#define NBATCH 256
#define NB    (NBATCH + NPAIR)   // 368 blocks; batches first (producers)
#define FXS   1048576.0          // 2^20 fixed-point scale

// ---------------- device scratch (fully rewritten every launch) -------------
__device__ float     g_mdT[Pn * Bn];   // transposed min_distances [p][b]
__device__ int       g_cidx[Bn][12];   // 11 smallest md indices per batch
__device__ float     g_cval[Bn][12];   // their values (ascending)
__device__ long long g_fx[8];          // 0:tl 1:l1 2:clst 3:sep 4:aop 5:oc
__device__ long long g_ent_fx[Cn];     // per-concept BCE sums (fixed point)
__device__ int       g_bar;            // batch publications (target NBATCH)
__device__ int       g_done;

__device__ __forceinline__ void fxadd(long long* p, float v) {
    atomicAdd((unsigned long long*)p,
              (unsigned long long)__double2ll_rn((double)v * FXS));
}

// order-preserving float->uint (monotonic)
__device__ __forceinline__ unsigned f2ord(float f) {
    unsigned u = __float_as_uint(f);
    return (u & 0x80000000u) ? ~u : (u | 0x80000000u);
}

// ---------------------------------------------------------------------------
// warp top-10 LARGEST (ties -> lower index) via REDUX -> smem (local only).
__device__ __forceinline__ void topk10_local(const float* s, int* oidx,
                                             unsigned long long* omask) {
    const int lane = threadIdx.x & 31;
    unsigned key[7];
    #pragma unroll
    for (int k = 0; k < 7; k++) {
        int p = lane + 32 * k;
        key[k] = (p < Pn) ? f2ord(s[p]) : 0u;
    }
    unsigned used = 0;
    unsigned long long mask[4] = {0ull, 0ull, 0ull, 0ull};
    #pragma unroll
    for (int it = 0; it < 10; it++) {
        unsigned bk = 0u; unsigned bi = 0xffffffffu;
        #pragma unroll
        for (int k = 0; k < 7; k++) {
            if (!((used >> k) & 1u) && key[k] > bk) { bk = key[k]; bi = lane + 32u * k; }
        }
        unsigned wmax = __reduce_max_sync(0xffffffffu, bk);
        unsigned cand = (bk == wmax) ? bi : 0xffffffffu;
        unsigned widx = __reduce_min_sync(0xffffffffu, cand);
        if ((widx & 31u) == (unsigned)lane) used |= 1u << (widx >> 5);
        if (lane == 0) { mask[widx >> 6] |= 1ull << (widx & 63u); oidx[it] = (int)widx; }
    }
    if (lane == 0) {
        #pragma unroll
        for (int w = 0; w < 4; w++) omask[w] = mask[w];
    }
}

// warp 11-SMALLEST (ascending; ties -> lower index) -> global lists (lane0).
__device__ __forceinline__ void mink11_global(const float* s, int* ci, float* cv) {
    const int lane = threadIdx.x & 31;
    unsigned key[7];
    #pragma unroll
    for (int k = 0; k < 7; k++) {
        int p = lane + 32 * k;
        key[k] = (p < Pn) ? f2ord(s[p]) : 0xffffffffu;
    }
    unsigned used = 0;
    #pragma unroll
    for (int it = 0; it < 11; it++) {
        unsigned bk = 0xffffffffu; unsigned bi = 0xffffffffu;
        #pragma unroll
        for (int k = 0; k < 7; k++) {
            if (!((used >> k) & 1u) && key[k] < bk) { bk = key[k]; bi = lane + 32u * k; }
        }
        unsigned wmin = __reduce_min_sync(0xffffffffu, bk);
        unsigned cand = (bk == wmin) ? bi : 0xffffffffu;
        unsigned widx = __reduce_min_sync(0xffffffffu, cand);
        if ((widx & 31u) == (unsigned)lane) used |= 1u << (widx >> 5);
        if (lane == 0) { ci[it] = (int)widx; cv[it] = s[widx]; }
    }
}

// block sum over 256 threads (valid at t==0).
__device__ __forceinline__ float bsum256(float v, float* s, int t) {
    __syncthreads();
    #pragma unroll
    for (int off = 16; off; off >>= 1) v += __shfl_down_sync(0xffffffffu, v, off);
    if ((t & 31) == 0) s[t >> 5] = v;
    __syncthreads();
    float r = 0.f;
    if (t == 0) {
        #pragma unroll
        for (int i = 0; i < 8; i++) r += s[i];
    }
    return r;
}

// ---------------------------------------------------------------------------
__global__ __launch_bounds__(256) void fused(const float* __restrict__ proto,
                                             const float* __restrict__ mind,
                                             const float* __restrict__ cy,
                                             const float* __restrict__ tlog,
                                             const int* __restrict__ tt,
                                             const float* __restrict__ wgt,
                                             const float* __restrict__ msk,
                                             const float* __restrict__ cx,
                                             float* __restrict__ out) {
    __shared__ float rA[Pn * Dn];
    __shared__ float rB[Pn * Dn];
    __shared__ float sA[Pn];
    __shared__ float sB[Pn];
    __shared__ float part[Pn];
    __shared__ float invn[2][Dn];
    __shared__ int   idxA[10], idxB[10];
    __shared__ unsigned long long mskA[4], mskB[4];
    __shared__ float reds[8];
    __shared__ int   amLast;

    const int bid  = blockIdx.x;
    const int t    = threadIdx.x;
    const int lane = t & 31;
    const int w    = t >> 5;

    if (bid < NBATCH) {
        // ============== per-batch PRODUCER block (b = bid) ==================
        const int b = bid;
        if (t < Pn) {
            float v = mind[b * Pn + t];
            sA[t] = v;
            g_mdT[t * Bn + b] = v;     // transposed scratch for pair blocks
            __threadfence();            // order my store before the release
        }
        if (t < Cn) sB[t] = cy[b * Cn + t];   // FIXED: full cy coverage
        __syncthreads();

        if (w == 0) {
            mink11_global(sA, g_cidx[b], g_cval[b]);
            if (lane == 0) {
                __threadfence();        // order candidate writes
                atomicAdd(&g_bar, 1);   // release (covers mdT via fence+bar)
            }
        } else if (w == 1) {
            // log-softmax target loss
            float v[7];
            float mx = -1e30f;
            #pragma unroll
            for (int k = 0; k < 7; k++) {
                int p = lane + 32 * k;
                v[k] = (p < NCLSn) ? tlog[b * NCLSn + p] : -1e30f;
                mx = fmaxf(mx, v[k]);
            }
            #pragma unroll
            for (int off = 16; off; off >>= 1)
                mx = fmaxf(mx, __shfl_xor_sync(0xffffffffu, mx, off));
            float se = 0.f;
            #pragma unroll
            for (int k = 0; k < 7; k++) {
                int p = lane + 32 * k;
                if (p < NCLSn) se += expf(v[k] - mx);
            }
            #pragma unroll
            for (int off = 16; off; off >>= 1)
                se += __shfl_xor_sync(0xffffffffu, se, off);
            if (lane == 0) {
                int cls = tt[b];
                fxadd(&g_fx[0], -(tlog[b * NCLSn + cls] - mx - logf(se)));
            }
        } else if (w == 2) {
            // l1 slice [b*175, b*175+175)
            float lp = 0.f;
            int base = b * 175;
            #pragma unroll
            for (int k = 0; k < 6; k++) {
                int i = lane + 32 * k;
                if (i < 175) lp += fabsf(wgt[base + i] * msk[base + i]);
            }
            #pragma unroll
            for (int off = 16; off; off >>= 1)
                lp += __shfl_down_sync(0xffffffffu, lp, off);
            if (lane == 0) fxadd(&g_fx[1], lp);
        } else if (w >= 4) {
            // BCE element (b, c=t-128): row-major coalesced
            int c = t - 128;
            if (c < Cn) {
                float x = cx[b * Cn + c];
                float y = sB[c];
                float bce = fmaxf(x, 0.f) + log1pf(expf(-fabsf(x))) - x * y;
                fxadd(&g_ent_fx[c], bce);
            }
        }

    } else {
        // ============== pair CONSUMER block: proto rows c, c+C ==============
        const int c = bid - NBATCH;

        // prefetch my batch's cy[b][c] (b = t); uncoalesced but early + MLP=1
        float cycol = cy[(size_t)t * Cn + c];

        // row sums straight from global (topk critical path)
        if (t < Pn) {
            const float2* ra = (const float2*)(proto + ((size_t)c * Pn + t) * Dn);
            const float2* rb = (const float2*)(proto + ((size_t)(c + Cn) * Pn + t) * Dn);
            float a = 0.f, b2 = 0.f;
            #pragma unroll
            for (int k = 0; k < 5; k++) {
                float2 va = ra[k]; a += va.x + va.y;
                float2 vb = rb[k]; b2 += vb.x + vb.y;
            }
            sA[t] = a; sB[t] = b2;
        }
        __syncthreads();

        // warps 0/1: LOCAL topk; warps 2-7: stage tile for ortho
        if (w == 0) {
            topk10_local(sA, idxA, mskA);
        } else if (w == 1) {
            topk10_local(sB, idxB, mskB);
        } else {
            const float4* pA = (const float4*)(proto + (size_t)c * Pn * Dn);
            const float4* pB = (const float4*)(proto + (size_t)(c + Cn) * Pn * Dn);
            for (int i = t - 64; i < (Pn * Dn) / 4; i += 192) {
                ((float4*)rA)[i] = pA[i];
                ((float4*)rB)[i] = pB[i];
            }
        }
        __syncthreads();

        // norms
        if (t < Pn) {
            int which = t / 100, rem = t % 100;
            int d = rem / 10, seg = rem % 10;
            const float* r = which ? rB : rA;
            float s = 0.f;
            #pragma unroll
            for (int p = seg * 20; p < seg * 20 + 20; p++) {
                float v = r[p * Dn + d]; s += v * v;
            }
            part[t] = s;
        }
        __syncthreads();
        if (t < 20) {
            int which = t / 10, d = t % 10;
            float s = 0.f;
            #pragma unroll
            for (int seg = 0; seg < 10; seg++) s += part[which * 100 + d * 10 + seg];
            invn[which][d] = rsqrtf(fmaxf(s, 1e-16f));
        }
        __syncthreads();

        // ortho partials (one row per thread)
        float aop = 0.f, oc = 0.f;
        if (t < Pn) {
            float ua = 0.f, ub = 0.f;
            #pragma unroll
            for (int d = 0; d < Dn; d++) {
                ua += rA[t * Dn + d] * invn[0][d];
                ub += rB[t * Dn + d] * invn[1][d];
            }
            aop = ua * ua + ub * ub;
            oc  = ua * ub;
        }
        float sa = bsum256(aop, reds, t);
        float so = bsum256(oc, reds, t);
        if (t == 0) { fxadd(&g_fx[4], sa); fxadd(&g_fx[5], so); }

        // wait for all batch publications (should be already met)
        if (t == 0) {
            while (*((volatile int*)&g_bar) < NBATCH) {}
        }
        __syncthreads();
        __threadfence();

        // clst/sep for this concept across all batches: thread = batch b
        {
            const int b = t;
            bool pos = (cycol > 0.5f);
            // coalesced: all threads read the same 20 mdT rows
            float mA = 1e30f, mB = 1e30f;
            #pragma unroll
            for (int k = 0; k < 10; k++) {
                mA = fminf(mA, g_mdT[idxA[k] * Bn + b]);
                mB = fminf(mB, g_mdT[idxB[k] * Bn + b]);
            }
            float m1 = pos ? mA : mB;

            unsigned long long w0 = pos ? mskB[0] : mskA[0];
            unsigned long long w1 = pos ? mskB[1] : mskA[1];
            unsigned long long w2 = pos ? mskB[2] : mskA[2];
            unsigned long long w3 = pos ? mskB[3] : mskA[3];
            float m2 = 1e30f;
            #pragma unroll
            for (int k = 0; k < 11; k++) {
                int id = g_cidx[b][k];
                unsigned long long wsel = (id < 64) ? w0 : (id < 128) ? w1
                                        : (id < 192) ? w2 : w3;
                if (!((wsel >> (id & 63)) & 1ull)) { m2 = g_cval[b][k]; break; }
            }

            float s1 = bsum256(m1, reds, t);
            float s2 = bsum256(m2, reds, t);
            if (t == 0) { fxadd(&g_fx[2], s1); fxadd(&g_fx[3], s2); }
        }
    }

    // =================== last-block finale ==================================
    __threadfence();
    if (t == 0) amLast = (atomicAdd(&g_done, 1) == NB - 1);
    __syncthreads();
    if (amLast) {
        __threadfence();
        float ents_c = 0.f;
        if (t < Cn) {
            ents_c = (float)((double)g_ent_fx[t] / FXS);
            out[1 + t] = ents_c / (float)Bn;
        }
        float s_ent = bsum256(ents_c, reds, t);
        if (t == 0) {
            float tls = (float)((double)g_fx[0] / FXS);
            float l1  = (float)((double)g_fx[1] / FXS);
            float cls = (float)((double)g_fx[2] / FXS);
            float sps = (float)((double)g_fx[3] / FXS);
            float ops = (float)((double)g_fx[4] / FXS);
            float ocs = (float)((double)g_fx[5] / FXS);

            float target_loss = tls / (float)Bn;
            float entropy     = s_ent / (float)(Bn * Cn);
            float clst        = cls / (float)(Bn * Cn);
            float sep         = sps / (float)(Bn * Cn);
            float ortho_p     = ops / (float)(Dn * Cn * 2) - 1.0f;
            float ortho_c     = ocs / (float)(Dn * Cn);
            float summed = entropy + 0.8f * clst + (-0.08f) * sep
                         + 1e-4f * l1 + ortho_p + ortho_c;
            out[0]   = target_loss;
            out[113] = summed;
            out[114] = target_loss + summed;
            out[115] = entropy;
            out[116] = clst;
            out[117] = sep;
            out[118] = l1;
            out[119] = ortho_p;
            out[120] = ortho_c;
        }
        __syncthreads();
        // reset accumulators for next graph replay (we are provably last)
        if (t < Cn) g_ent_fx[t] = 0;
        if (t < 8)  g_fx[t] = 0;
        if (t == 0) { g_bar = 0; g_done = 0; }
    }
}

// ---------------------------------------------------------------------------
extern "C" void kernel_launch(void* const* d_in, const int* in_sizes, int n_in,
                              void* d_out, int out_size) {
    const float* cx    = (const float*)d_in[0];
    const float* cy    = (const float*)d_in[1];
    const float* mind  = (const float*)d_in[2];
    const float* proto = (const float*)d_in[3];
    const float* tlog  = (const float*)d_in[4];
    const int*   tt    = (const int*)d_in[5];
    const float* wgt   = (const float*)d_in[6];
    const float* msk   = (const float*)d_in[7];
    float* out = (float*)d_out;

    fused<<<NB, 256>>>(proto, mind, cy, tlog, tt, wgt, msk, cx, out);
}

// round 13
// speedup vs baseline: 1.1372x; 1.1372x over previous
#include <cuda_runtime.h>
#include <math.h>

#define Bn    256
#define Cn    112
#define C2    224
#define Pn    200
#define Dn    10
#define NCLSn 200
#define NPAIR 112
#define NBATCH 256
#define NB    (NPAIR + NBATCH)   // 368 blocks; pairs first (producers)
#define FXS   1048576.0          // 2^20 fixed-point scale

// ---------------- device scratch (fully rewritten every launch) -------------
__device__ unsigned long long g_mask[C2][4];
__device__ int       g_gidx[C2][10];
__device__ long long g_fx[8];          // 0:tl 1:l1 2:clst 3:sep 4:aop 5:oc
__device__ long long g_ent_fx[Cn];     // per-concept BCE sums (fixed point)
__device__ int       g_bar;            // topk publications (target C2)
__device__ int       g_done;

__device__ __forceinline__ void fxadd(long long* p, float v) {
    atomicAdd((unsigned long long*)p,
              (unsigned long long)__double2ll_rn((double)v * FXS));
}

// order-preserving float->uint (monotonic)
__device__ __forceinline__ unsigned f2ord(float f) {
    unsigned u = __float_as_uint(f);
    return (u & 0x80000000u) ? ~u : (u | 0x80000000u);
}

// ---------------------------------------------------------------------------
// warp top-10 LARGEST (ties -> lower index) via REDUX; publishes + releases.
__device__ __forceinline__ void topk10_publish(const float* s, int r) {
    const int lane = threadIdx.x & 31;
    unsigned key[7];
    #pragma unroll
    for (int k = 0; k < 7; k++) {
        int p = lane + 32 * k;
        key[k] = (p < Pn) ? f2ord(s[p]) : 0u;
    }
    unsigned used = 0;
    unsigned long long mask[4] = {0ull, 0ull, 0ull, 0ull};
    #pragma unroll
    for (int it = 0; it < 10; it++) {
        unsigned bk = 0u; unsigned bi = 0xffffffffu;
        #pragma unroll
        for (int k = 0; k < 7; k++) {
            if (!((used >> k) & 1u) && key[k] > bk) { bk = key[k]; bi = lane + 32u * k; }
        }
        unsigned wmax = __reduce_max_sync(0xffffffffu, bk);
        unsigned cand = (bk == wmax) ? bi : 0xffffffffu;
        unsigned widx = __reduce_min_sync(0xffffffffu, cand);
        if ((widx & 31u) == (unsigned)lane) used |= 1u << (widx >> 5);
        if (lane == 0) { mask[widx >> 6] |= 1ull << (widx & 63u); g_gidx[r][it] = (int)widx; }
    }
    if (lane == 0) {
        #pragma unroll
        for (int w = 0; w < 4; w++) g_mask[r][w] = mask[w];
        __threadfence();          // release: data before counter bump
        atomicAdd(&g_bar, 1);
    }
}

// warp 11-SMALLEST (ascending; ties -> lower index) into smem lists.
__device__ __forceinline__ void mink11_local(const float* s, int* ci, float* cv) {
    const int lane = threadIdx.x & 31;
    unsigned key[7];
    #pragma unroll
    for (int k = 0; k < 7; k++) {
        int p = lane + 32 * k;
        key[k] = (p < Pn) ? f2ord(s[p]) : 0xffffffffu;
    }
    unsigned used = 0;
    #pragma unroll
    for (int it = 0; it < 11; it++) {
        unsigned bk = 0xffffffffu; unsigned bi = 0xffffffffu;
        #pragma unroll
        for (int k = 0; k < 7; k++) {
            if (!((used >> k) & 1u) && key[k] < bk) { bk = key[k]; bi = lane + 32u * k; }
        }
        unsigned wmin = __reduce_min_sync(0xffffffffu, bk);
        unsigned cand = (bk == wmin) ? bi : 0xffffffffu;
        unsigned widx = __reduce_min_sync(0xffffffffu, cand);
        if ((widx & 31u) == (unsigned)lane) used |= 1u << (widx >> 5);
        if (lane == 0) { ci[it] = (int)widx; cv[it] = s[widx]; }
    }
}

// block sum over 256 threads (valid at t==0).
__device__ __forceinline__ float bsum256(float v, float* s, int t) {
    __syncthreads();
    #pragma unroll
    for (int off = 16; off; off >>= 1) v += __shfl_down_sync(0xffffffffu, v, off);
    if ((t & 31) == 0) s[t >> 5] = v;
    __syncthreads();
    float r = 0.f;
    if (t == 0) {
        #pragma unroll
        for (int i = 0; i < 8; i++) r += s[i];
    }
    return r;
}

// ---------------------------------------------------------------------------
__global__ __launch_bounds__(256) void fused(const float* __restrict__ proto,
                                             const float* __restrict__ mind,
                                             const float* __restrict__ cy,
                                             const float* __restrict__ tlog,
                                             const int* __restrict__ tt,
                                             const float* __restrict__ wgt,
                                             const float* __restrict__ msk,
                                             const float* __restrict__ cx,
                                             float* __restrict__ out) {
    __shared__ float sA[Pn];            // rowsums A / md
    __shared__ float sB[Pn];            // rowsums B / cy row
    __shared__ float partw[8][20];      // per-warp column sq-norm partials
    __shared__ float invn[2][Dn];
    __shared__ int   candi[11];
    __shared__ float candv[11];
    __shared__ float reds[8];
    __shared__ int   amLast;

    const int bid  = blockIdx.x;
    const int t    = threadIdx.x;
    const int lane = t & 31;
    const int w    = t >> 5;

    if (bid < NPAIR) {
        // ============== pair block: proto rows c, c+C (register-resident) ===
        const int c = bid;
        float vA[Dn], vB[Dn];
        #pragma unroll
        for (int d = 0; d < Dn; d++) { vA[d] = 0.f; vB[d] = 0.f; }
        if (t < Pn) {
            const float2* ra = (const float2*)(proto + ((size_t)c * Pn + t) * Dn);
            const float2* rb = (const float2*)(proto + ((size_t)(c + Cn) * Pn + t) * Dn);
            float a = 0.f, b2 = 0.f;
            #pragma unroll
            for (int k = 0; k < 5; k++) {
                float2 xa = ra[k]; vA[2 * k] = xa.x; vA[2 * k + 1] = xa.y; a += xa.x + xa.y;
                float2 xb = rb[k]; vB[2 * k] = xb.x; vB[2 * k + 1] = xb.y; b2 += xb.x + xb.y;
            }
            sA[t] = a; sB[t] = b2;
        }
        __syncthreads();

        // warps 0/1: topk + publish (early release); then all warps norm-reduce
        if (w == 0)      topk10_publish(sA, c);
        else if (w == 1) topk10_publish(sB, c + Cn);

        {   // per-warp column sq-norm partials, 20 ILP-interleaved shfl trees
            float qa[Dn], qb[Dn];
            #pragma unroll
            for (int d = 0; d < Dn; d++) { qa[d] = vA[d] * vA[d]; qb[d] = vB[d] * vB[d]; }
            #pragma unroll
            for (int off = 16; off; off >>= 1) {
                #pragma unroll
                for (int d = 0; d < Dn; d++) {
                    qa[d] += __shfl_down_sync(0xffffffffu, qa[d], off);
                    qb[d] += __shfl_down_sync(0xffffffffu, qb[d], off);
                }
            }
            if (lane == 0) {
                #pragma unroll
                for (int d = 0; d < Dn; d++) {
                    partw[w][d]      = qa[d];
                    partw[w][10 + d] = qb[d];
                }
            }
        }
        __syncthreads();
        if (t < 20) {
            float s = 0.f;
            #pragma unroll
            for (int i = 0; i < 8; i++) s += partw[i][t];
            invn[t / 10][t % 10] = rsqrtf(fmaxf(s, 1e-16f));
        }
        __syncthreads();

        // ortho partials from registers
        float aop = 0.f, oc = 0.f;
        if (t < Pn) {
            float ua = 0.f, ub = 0.f;
            #pragma unroll
            for (int d = 0; d < Dn; d++) {
                ua += vA[d] * invn[0][d];
                ub += vB[d] * invn[1][d];
            }
            aop = ua * ua + ub * ub;
            oc  = ua * ub;
        }
        float sa = bsum256(aop, reds, t);
        float so = bsum256(oc, reds, t);
        if (t == 0) { fxadd(&g_fx[4], sa); fxadd(&g_fx[5], so); }

    } else {
        // ============== per-batch block (b) =================================
        const int b = bid - NPAIR;
        if (t < Pn) sA[t] = mind[b * Pn + t];
        if (t < Cn) sB[t] = cy[b * Cn + t];
        __syncthreads();

        if (w == 0) {
            mink11_local(sA, candi, candv);
        } else if (w == 1) {
            // log-softmax target loss
            float v[7];
            float mx = -1e30f;
            #pragma unroll
            for (int k = 0; k < 7; k++) {
                int p = lane + 32 * k;
                v[k] = (p < NCLSn) ? tlog[b * NCLSn + p] : -1e30f;
                mx = fmaxf(mx, v[k]);
            }
            #pragma unroll
            for (int off = 16; off; off >>= 1)
                mx = fmaxf(mx, __shfl_xor_sync(0xffffffffu, mx, off));
            float se = 0.f;
            #pragma unroll
            for (int k = 0; k < 7; k++) {
                int p = lane + 32 * k;
                if (p < NCLSn) se += expf(v[k] - mx);
            }
            #pragma unroll
            for (int off = 16; off; off >>= 1)
                se += __shfl_xor_sync(0xffffffffu, se, off);
            if (lane == 0) {
                int cls = tt[b];
                fxadd(&g_fx[0], -(tlog[b * NCLSn + cls] - mx - logf(se)));
            }
        } else if (w == 2) {
            // l1 slice [b*175, b*175+175)
            float lp = 0.f;
            int base = b * 175;
            #pragma unroll
            for (int k = 0; k < 6; k++) {
                int i = lane + 32 * k;
                if (i < 175) lp += fabsf(wgt[base + i] * msk[base + i]);
            }
            #pragma unroll
            for (int off = 16; off; off >>= 1)
                lp += __shfl_down_sync(0xffffffffu, lp, off);
            if (lane == 0) fxadd(&g_fx[1], lp);
        } else if (w >= 4) {
            // BCE element (b, c=t-128): row-major coalesced
            int c = t - 128;
            if (c < Cn) {
                float x = cx[b * Cn + c];
                float y = sB[c];
                float bce = fmaxf(x, 0.f) + log1pf(expf(-fabsf(x))) - x * y;
                fxadd(&g_ent_fx[c], bce);
            }
        }

        // wait for all 224 topk publications (single cached counter)
        if (t == 0) {
            while (*((volatile int*)&g_bar) < C2) {}
        }
        __syncthreads();
        __threadfence();

        float m1s = 0.f, m2s = 0.f;
        if (t < Cn) {
            const int c = t;
            float yv = sB[c];
            bool pos = (yv > 0.5f);
            int r1 = pos ? c : c + Cn;
            int r2 = pos ? c + Cn : c;
            const int* gi = g_gidx[r1];
            float m1 = 1e30f;
            #pragma unroll
            for (int k = 0; k < 10; k++) m1 = fminf(m1, sA[gi[k]]);
            unsigned long long w0 = g_mask[r2][0], w1 = g_mask[r2][1];
            unsigned long long w2 = g_mask[r2][2], w3 = g_mask[r2][3];
            float m2 = 1e30f;
            #pragma unroll
            for (int k = 0; k < 11; k++) {
                int id = candi[k];
                unsigned long long wsel = (id < 64) ? w0 : (id < 128) ? w1
                                        : (id < 192) ? w2 : w3;
                if (!((wsel >> (id & 63)) & 1ull)) { m2 = candv[k]; break; }
            }
            m1s = m1; m2s = m2;
        }
        float s1 = bsum256(m1s, reds, t);
        float s2 = bsum256(m2s, reds, t);
        if (t == 0) { fxadd(&g_fx[2], s1); fxadd(&g_fx[3], s2); }
    }

    // =================== last-block finale ==================================
    __threadfence();
    if (t == 0) amLast = (atomicAdd(&g_done, 1) == NB - 1);
    __syncthreads();
    if (amLast) {
        __threadfence();
        float ents_c = 0.f;
        if (t < Cn) {
            ents_c = (float)((double)g_ent_fx[t] / FXS);
            out[1 + t] = ents_c / (float)Bn;
        }
        float s_ent = bsum256(ents_c, reds, t);
        if (t == 0) {
            float tls = (float)((double)g_fx[0] / FXS);
            float l1  = (float)((double)g_fx[1] / FXS);
            float cls = (float)((double)g_fx[2] / FXS);
            float sps = (float)((double)g_fx[3] / FXS);
            float ops = (float)((double)g_fx[4] / FXS);
            float ocs = (float)((double)g_fx[5] / FXS);

            float target_loss = tls / (float)Bn;
            float entropy     = s_ent / (float)(Bn * Cn);
            float clst        = cls / (float)(Bn * Cn);
            float sep         = sps / (float)(Bn * Cn);
            float ortho_p     = ops / (float)(Dn * Cn * 2) - 1.0f;
            float ortho_c     = ocs / (float)(Dn * Cn);
            float summed = entropy + 0.8f * clst + (-0.08f) * sep
                         + 1e-4f * l1 + ortho_p + ortho_c;
            out[0]   = target_loss;
            out[113] = summed;
            out[114] = target_loss + summed;
            out[115] = entropy;
            out[116] = clst;
            out[117] = sep;
            out[118] = l1;
            out[119] = ortho_p;
            out[120] = ortho_c;
        }
        __syncthreads();
        // reset accumulators for next graph replay (we are provably last)
        if (t < Cn) g_ent_fx[t] = 0;
        if (t < 8)  g_fx[t] = 0;
        if (t == 0) { g_bar = 0; g_done = 0; }
    }
}

// ---------------------------------------------------------------------------
extern "C" void kernel_launch(void* const* d_in, const int* in_sizes, int n_in,
                              void* d_out, int out_size) {
    const float* cx    = (const float*)d_in[0];
    const float* cy    = (const float*)d_in[1];
    const float* mind  = (const float*)d_in[2];
    const float* proto = (const float*)d_in[3];
    const float* tlog  = (const float*)d_in[4];
    const int*   tt    = (const int*)d_in[5];
    const float* wgt   = (const float*)d_in[6];
    const float* msk   = (const float*)d_in[7];
    float* out = (float*)d_out;

    fused<<<NB, 256>>>(proto, mind, cy, tlog, tt, wgt, msk, cx, out);
}

// round 16
// speedup vs baseline: 1.1783x; 1.0362x over previous
#include <cuda_runtime.h>
#include <math.h>

#define Bn    256
#define Cn    112
#define C2    224
#define Pn    200
#define Dn    10
#define NCLSn 200
#define NPAIR 112
#define NBATCH 256
#define NB    (NPAIR + NBATCH)   // 368 blocks; pairs first (producers)
#define FXS   1048576.0          // 2^20 fixed-point scale

// ---------------- device scratch (fully rewritten every launch) -------------
__device__ unsigned long long g_mask[C2][4];
__device__ int       g_gidx[C2][10];
__device__ long long g_fx[8];          // 0:tl 1:l1 2:clst 3:sep 4:aop 5:oc
__device__ long long g_ent_fx[Cn];     // per-concept BCE sums (fixed point)
__device__ int       g_bar;            // pair publications (target NPAIR)
__device__ int       g_done;

__device__ __forceinline__ void fxadd(long long* p, float v) {
    atomicAdd((unsigned long long*)p,
              (unsigned long long)__double2ll_rn((double)v * FXS));
}

// order-preserving float->uint (monotonic)
__device__ __forceinline__ unsigned f2ord(float f) {
    unsigned u = __float_as_uint(f);
    return (u & 0x80000000u) ? ~u : (u | 0x80000000u);
}

// ---------------------------------------------------------------------------
// warp top-10 LARGEST (ties -> lower index) via REDUX; lane0 writes + fence.
__device__ __forceinline__ void topk10_redux(const float* s, int r) {
    const int lane = threadIdx.x & 31;
    unsigned key[7];
    #pragma unroll
    for (int k = 0; k < 7; k++) {
        int p = lane + 32 * k;
        key[k] = (p < Pn) ? f2ord(s[p]) : 0u;
    }
    unsigned used = 0;
    unsigned long long mask[4] = {0ull, 0ull, 0ull, 0ull};
    #pragma unroll
    for (int it = 0; it < 10; it++) {
        unsigned bk = 0u; unsigned bi = 0xffffffffu;
        #pragma unroll
        for (int k = 0; k < 7; k++) {
            if (!((used >> k) & 1u) && key[k] > bk) { bk = key[k]; bi = lane + 32u * k; }
        }
        unsigned wmax = __reduce_max_sync(0xffffffffu, bk);
        unsigned cand = (bk == wmax) ? bi : 0xffffffffu;
        unsigned widx = __reduce_min_sync(0xffffffffu, cand);
        if ((widx & 31u) == (unsigned)lane) used |= 1u << (widx >> 5);
        if (lane == 0) { mask[widx >> 6] |= 1ull << (widx & 63u); g_gidx[r][it] = (int)widx; }
    }
    if (lane == 0) {
        #pragma unroll
        for (int w = 0; w < 4; w++) g_mask[r][w] = mask[w];
        __threadfence();   // release: data before counter bump
    }
}

// warp 11-SMALLEST (ascending; ties -> lower index) into smem lists.
__device__ __forceinline__ void mink11_redux(const float* s, int* ci, float* cv) {
    const int lane = threadIdx.x & 31;
    unsigned key[7];
    #pragma unroll
    for (int k = 0; k < 7; k++) {
        int p = lane + 32 * k;
        key[k] = (p < Pn) ? f2ord(s[p]) : 0xffffffffu;
    }
    unsigned used = 0;
    #pragma unroll
    for (int it = 0; it < 11; it++) {
        unsigned bk = 0xffffffffu; unsigned bi = 0xffffffffu;
        #pragma unroll
        for (int k = 0; k < 7; k++) {
            if (!((used >> k) & 1u) && key[k] < bk) { bk = key[k]; bi = lane + 32u * k; }
        }
        unsigned wmin = __reduce_min_sync(0xffffffffu, bk);
        unsigned cand = (bk == wmin) ? bi : 0xffffffffu;
        unsigned widx = __reduce_min_sync(0xffffffffu, cand);
        if ((widx & 31u) == (unsigned)lane) used |= 1u << (widx >> 5);
        if (lane == 0) { ci[it] = (int)widx; cv[it] = s[widx]; }
    }
}

// single block sum over 256 threads (valid at t==0).
__device__ __forceinline__ float bsum256(float v, float* s, int t) {
    __syncthreads();
    #pragma unroll
    for (int off = 16; off; off >>= 1) v += __shfl_down_sync(0xffffffffu, v, off);
    if ((t & 31) == 0) s[t >> 5] = v;
    __syncthreads();
    float r = 0.f;
    if (t == 0) {
        #pragma unroll
        for (int i = 0; i < 8; i++) r += s[i];
    }
    return r;
}

// fused dual block sum (one tree, one sync pair) -> valid at t==0.
__device__ __forceinline__ float2 bsum256x2(float a, float b, float2* s, int t) {
    __syncthreads();
    #pragma unroll
    for (int off = 16; off; off >>= 1) {
        a += __shfl_down_sync(0xffffffffu, a, off);
        b += __shfl_down_sync(0xffffffffu, b, off);
    }
    if ((t & 31) == 0) s[t >> 5] = make_float2(a, b);
    __syncthreads();
    float2 r = make_float2(0.f, 0.f);
    if (t == 0) {
        #pragma unroll
        for (int i = 0; i < 8; i++) { r.x += s[i].x; r.y += s[i].y; }
    }
    return r;
}

// ---------------------------------------------------------------------------
__global__ __launch_bounds__(256) void fused(const float* __restrict__ proto,
                                             const float* __restrict__ mind,
                                             const float* __restrict__ cy,
                                             const float* __restrict__ tlog,
                                             const int* __restrict__ tt,
                                             const float* __restrict__ wgt,
                                             const float* __restrict__ msk,
                                             const float* __restrict__ cx,
                                             float* __restrict__ out) {
    __shared__ float rA[Pn * Dn];
    __shared__ float rB[Pn * Dn];
    __shared__ float sA[Pn];
    __shared__ float sB[Pn];
    __shared__ float part[Pn];
    __shared__ float invn[2][Dn];
    __shared__ int   candi[11];
    __shared__ float candv[11];
    __shared__ float reds[8];
    __shared__ float2 reds2[8];
    __shared__ int   amLast;

    const int bid  = blockIdx.x;
    const int t    = threadIdx.x;
    const int lane = t & 31;
    const int w    = t >> 5;

    if (bid < NPAIR) {
        // =================== pair block: proto rows c, c+C ==================
        const int c = bid;

        // phase 0: row sums straight from global (critical path for topk)
        if (t < Pn) {
            const float2* ra = (const float2*)(proto + ((size_t)c * Pn + t) * Dn);
            const float2* rb = (const float2*)(proto + ((size_t)(c + Cn) * Pn + t) * Dn);
            float a = 0.f, b2 = 0.f;
            #pragma unroll
            for (int k = 0; k < 5; k++) {
                float2 va = ra[k]; a += va.x + va.y;
                float2 vb = rb[k]; b2 += vb.x + vb.y;
            }
            sA[t] = a; sB[t] = b2;
        }
        __syncthreads();

        // warps 0/1: topk + EARLY publish; warps 2-7: stage tile into smem
        if (w == 0) {
            topk10_redux(sA, c);
        } else if (w == 1) {
            topk10_redux(sB, c + Cn);
        } else {
            const float4* pA = (const float4*)(proto + (size_t)c * Pn * Dn);
            const float4* pB = (const float4*)(proto + (size_t)(c + Cn) * Pn * Dn);
            for (int i = t - 64; i < (Pn * Dn) / 4; i += 192) {
                ((float4*)rA)[i] = pA[i];
                ((float4*)rB)[i] = pB[i];
            }
        }
        if (w < 2) {
            asm volatile("bar.sync 1, 64;" ::: "memory");
            if (t == 0) atomicAdd(&g_bar, 1);    // one release per pair
        }
        __syncthreads();

        // norms
        if (t < Pn) {
            int which = t / 100, rem = t % 100;
            int d = rem / 10, seg = rem % 10;
            const float* r = which ? rB : rA;
            float s = 0.f;
            #pragma unroll
            for (int p = seg * 20; p < seg * 20 + 20; p++) {
                float v = r[p * Dn + d]; s += v * v;
            }
            part[t] = s;
        }
        __syncthreads();
        if (t < 20) {
            int which = t / 10, d = t % 10;
            float s = 0.f;
            #pragma unroll
            for (int seg = 0; seg < 10; seg++) s += part[which * 100 + d * 10 + seg];
            invn[which][d] = rsqrtf(fmaxf(s, 1e-16f));
        }
        __syncthreads();

        // ortho partials (one row per thread), fused dual reduction
        float aop = 0.f, oc = 0.f;
        if (t < Pn) {
            float ua = 0.f, ub = 0.f;
            #pragma unroll
            for (int d = 0; d < Dn; d++) {
                ua += rA[t * Dn + d] * invn[0][d];
                ub += rB[t * Dn + d] * invn[1][d];
            }
            aop = ua * ua + ub * ub;
            oc  = ua * ub;
        }
        float2 so = bsum256x2(aop, oc, reds2, t);
        if (t == 0) { fxadd(&g_fx[4], so.x); fxadd(&g_fx[5], so.y); }

    } else {
        // =================== per-batch block (b) ============================
        const int b = bid - NPAIR;
        if (t < Pn) sA[t] = mind[b * Pn + t];
        if (t < Cn) sB[t] = cy[b * Cn + t];
        __syncthreads();

        if (w == 0) {
            mink11_redux(sA, candi, candv);
        } else if (w == 1) {
            // log-softmax target loss
            float v[7];
            float mx = -1e30f;
            #pragma unroll
            for (int k = 0; k < 7; k++) {
                int p = lane + 32 * k;
                v[k] = (p < NCLSn) ? tlog[b * NCLSn + p] : -1e30f;
                mx = fmaxf(mx, v[k]);
            }
            #pragma unroll
            for (int off = 16; off; off >>= 1)
                mx = fmaxf(mx, __shfl_xor_sync(0xffffffffu, mx, off));
            float se = 0.f;
            #pragma unroll
            for (int k = 0; k < 7; k++) {
                int p = lane + 32 * k;
                if (p < NCLSn) se += expf(v[k] - mx);
            }
            #pragma unroll
            for (int off = 16; off; off >>= 1)
                se += __shfl_xor_sync(0xffffffffu, se, off);
            if (lane == 0) {
                int cls = tt[b];
                fxadd(&g_fx[0], -(tlog[b * NCLSn + cls] - mx - logf(se)));
            }
        } else if (w == 2) {
            // l1 slice [b*175, b*175+175)
            float lp = 0.f;
            int base = b * 175;
            #pragma unroll
            for (int k = 0; k < 6; k++) {
                int i = lane + 32 * k;
                if (i < 175) lp += fabsf(wgt[base + i] * msk[base + i]);
            }
            #pragma unroll
            for (int off = 16; off; off >>= 1)
                lp += __shfl_down_sync(0xffffffffu, lp, off);
            if (lane == 0) fxadd(&g_fx[1], lp);
        } else if (w >= 4) {
            // BCE element (b, c=t-128): row-major coalesced, hidden by wait
            int c = t - 128;
            if (c < Cn) {
                float x = cx[b * Cn + c];
                float y = sB[c];
                float bce = fmaxf(x, 0.f) + log1pf(expf(-fabsf(x))) - x * y;
                fxadd(&g_ent_fx[c], bce);
            }
        }

        // wait for all pair publications (single cached counter, one spinner)
        if (t == 0) {
            while (*((volatile int*)&g_bar) < NPAIR) {}
        }
        __syncthreads();
        __threadfence();

        float m1s = 0.f, m2s = 0.f;
        if (t < Cn) {
            const int c = t;
            float yv = sB[c];
            bool pos = (yv > 0.5f);
            int r1 = pos ? c : c + Cn;
            int r2 = pos ? c + Cn : c;
            const int* gi = g_gidx[r1];
            float m1 = 1e30f;
            #pragma unroll
            for (int k = 0; k < 10; k++) m1 = fminf(m1, sA[gi[k]]);
            unsigned long long w0 = g_mask[r2][0], w1 = g_mask[r2][1];
            unsigned long long w2 = g_mask[r2][2], w3 = g_mask[r2][3];
            float m2 = 1e30f;
            #pragma unroll
            for (int k = 0; k < 11; k++) {
                int id = candi[k];
                unsigned long long wsel = (id < 64) ? w0 : (id < 128) ? w1
                                        : (id < 192) ? w2 : w3;
                if (!((wsel >> (id & 63)) & 1ull)) { m2 = candv[k]; break; }
            }
            m1s = m1; m2s = m2;
        }
        float2 sc = bsum256x2(m1s, m2s, reds2, t);
        if (t == 0) { fxadd(&g_fx[2], sc.x); fxadd(&g_fx[3], sc.y); }
    }

    // =================== last-block finale ==================================
    __threadfence();
    if (t == 0) amLast = (atomicAdd(&g_done, 1) == NB - 1);
    __syncthreads();
    if (amLast) {
        __threadfence();
        float ents_c = 0.f;
        if (t < Cn) {
            ents_c = (float)((double)g_ent_fx[t] / FXS);
            out[1 + t] = ents_c / (float)Bn;
        }
        float s_ent = bsum256(ents_c, reds, t);
        if (t == 0) {
            float tls = (float)((double)g_fx[0] / FXS);
            float l1  = (float)((double)g_fx[1] / FXS);
            float cls = (float)((double)g_fx[2] / FXS);
            float sps = (float)((double)g_fx[3] / FXS);
            float ops = (float)((double)g_fx[4] / FXS);
            float ocs = (float)((double)g_fx[5] / FXS);

            float target_loss = tls / (float)Bn;
            float entropy     = s_ent / (float)(Bn * Cn);
            float clst        = cls / (float)(Bn * Cn);
            float sep         = sps / (float)(Bn * Cn);
            float ortho_p     = ops / (float)(Dn * Cn * 2) - 1.0f;
            float ortho_c     = ocs / (float)(Dn * Cn);
            float summed = entropy + 0.8f * clst + (-0.08f) * sep
                         + 1e-4f * l1 + ortho_p + ortho_c;
            out[0]   = target_loss;
            out[113] = summed;
            out[114] = target_loss + summed;
            out[115] = entropy;
            out[116] = clst;
            out[117] = sep;
            out[118] = l1;
            out[119] = ortho_p;
            out[120] = ortho_c;
        }
        __syncthreads();
        // reset accumulators for next graph replay (we are provably last)
        if (t < Cn) g_ent_fx[t] = 0;
        if (t < 8)  g_fx[t] = 0;
        if (t == 0) { g_bar = 0; g_done = 0; }
    }
}

// ---------------------------------------------------------------------------
extern "C" void kernel_launch(void* const* d_in, const int* in_sizes, int n_in,
                              void* d_out, int out_size) {
    const float* cx    = (const float*)d_in[0];
    const float* cy    = (const float*)d_in[1];
    const float* mind  = (const float*)d_in[2];
    const float* proto = (const float*)d_in[3];
    const float* tlog  = (const float*)d_in[4];
    const int*   tt    = (const int*)d_in[5];
    const float* wgt   = (const float*)d_in[6];
    const float* msk   = (const float*)d_in[7];
    float* out = (float*)d_out;

    fused<<<NB, 256>>>(proto, mind, cy, tlog, tt, wgt, msk, cx, out);
}